// round 2
// baseline (speedup 1.0000x reference)
#include <cuda_runtime.h>
#include <cuda_bf16.h>
#include <math.h>

#define N_ 50000
#define F_ 128
#define G_ 3
#define E_ 600000
#define NF ((size_t)N_ * F_)

// ------------------------- static device scratch -------------------------
__device__ __align__(16) float d_pre  [G_ * N_ * F_];
__device__ __align__(16) float d_conv1[G_ * N_ * F_];
__device__ __align__(16) float d_enc  [G_ * N_ * F_];
__device__ __align__(16) float d_own1 [G_ * N_ * F_];
__device__ __align__(16) float d_own2 [G_ * N_ * F_];
__device__ __align__(16) float d_oth2 [G_ * N_ * F_];
__device__ __align__(16) float d_tmp  [G_ * N_ * F_];
__device__ __align__(16) float d_decin[G_ * N_ * F_];   // also reused as oth1
__device__ __align__(16) float d_efin [G_ * N_ * F_];

__device__ int   d_deg   [G_ * N_];
__device__ int   d_rowptr[G_ * (N_ + 1)];
__device__ int   d_cur   [G_ * N_];
__device__ int   d_col   [G_ * E_];
__device__ __align__(16) float d_dinv  [G_ * N_];
__device__ float d_gv    [G_ * F_];
__device__ __align__(16) float d_u     [G_ * F_];
__device__ float d_parts [16];
__device__ int   d_e64;      // 1 if edge buffer is int64, 0 if int32

// ------------------------- edge dtype detection ---------------------------
// int64 little-endian with values in [0,50000): every odd 32-bit word is 0.
// int32: odd words are indices, overwhelmingly nonzero. Sample 4096 words.
__global__ void detect_dtype_k(const void* __restrict__ edges) {
    const unsigned int* w = (const unsigned int*)edges;
    __shared__ int any;
    if (threadIdx.x == 0) any = 0;
    __syncthreads();
    for (int i = threadIdx.x; i < 2048; i += blockDim.x)
        if (w[2 * i + 1] != 0u) any = 1;
    __syncthreads();
    if (threadIdx.x == 0) d_e64 = any ? 0 : 1;
}

__device__ __forceinline__ int load_edge(const void* edges, size_t idx, int e64) {
    if (e64) return (int)((const long long*)edges)[idx];
    return ((const int*)edges)[idx];
}

// ------------------------- small utility kernels -------------------------
__global__ void zero_deg_k() {
    int i = blockIdx.x * blockDim.x + threadIdx.x;
    if (i < G_ * N_) d_deg[i] = 0;
}

__global__ void zero_small_k() {
    int i = threadIdx.x;
    if (i < G_ * F_) d_gv[i] = 0.f;
    if (i < 16) d_parts[i] = 0.f;
}

__global__ void count_deg_k(const void* __restrict__ edges) {
    int i = blockIdx.x * blockDim.x + threadIdx.x;
    if (i >= G_ * E_) return;
    int e64 = d_e64;
    int g = i / E_, e = i - g * E_;
    int dst = load_edge(edges, (size_t)g * 2 * E_ + E_ + e, e64);
    atomicAdd(&d_deg[g * N_ + dst], 1);
}

__global__ void dinv_k() {
    int i = blockIdx.x * blockDim.x + threadIdx.x;
    if (i < G_ * N_) d_dinv[i] = rsqrtf((float)(d_deg[i] + 1));
}

// one block per graph; chunked Hillis-Steele inclusive scan
__global__ void scan_rowptr_k() {
    int g = blockIdx.x;
    __shared__ int sbuf[1024];
    __shared__ int soff;
    int tid = threadIdx.x;
    if (tid == 0) { soff = 0; d_rowptr[g * (N_ + 1)] = 0; }
    __syncthreads();
    for (int base = 0; base < N_; base += 1024) {
        int idx = base + tid;
        int v = (idx < N_) ? d_deg[g * N_ + idx] : 0;
        sbuf[tid] = v;
        __syncthreads();
        for (int s = 1; s < 1024; s <<= 1) {
            int t = (tid >= s) ? sbuf[tid - s] : 0;
            __syncthreads();
            sbuf[tid] += t;
            __syncthreads();
        }
        if (idx < N_) d_rowptr[g * (N_ + 1) + idx + 1] = soff + sbuf[tid];
        __syncthreads();
        if (tid == 0) soff += sbuf[1023];
        __syncthreads();
    }
}

__global__ void init_cur_k() {
    int i = blockIdx.x * blockDim.x + threadIdx.x;
    if (i >= G_ * N_) return;
    int g = i / N_, n = i - g * N_;
    d_cur[i] = d_rowptr[g * (N_ + 1) + n];
}

__global__ void fill_csr_k(const void* __restrict__ edges) {
    int i = blockIdx.x * blockDim.x + threadIdx.x;
    if (i >= G_ * E_) return;
    int e64 = d_e64;
    int g = i / E_, e = i - g * E_;
    int src = load_edge(edges, (size_t)g * 2 * E_ + e, e64);
    int dst = load_edge(edges, (size_t)g * 2 * E_ + E_ + e, e64);
    int pos = atomicAdd(&d_cur[g * N_ + dst], 1);
    d_col[(size_t)g * E_ + pos] = src;
}

// ------------------------- GEMM: Y[N,128] (+)= X[N,128] @ W[128,128] (+b) --
// block = 256 threads, tile 64 rows x 128 cols, K in chunks of 32
__global__ void __launch_bounds__(256) gemm_n128_k(
    const float* __restrict__ Xbase, const float* __restrict__ Wbase,
    const float* __restrict__ bbase, float* __restrict__ Ybase,
    int wstride, int bstride, int accumulate)
{
    int g = blockIdx.y;
    const float* X = Xbase + (size_t)g * NF;
    const float* W = Wbase + (size_t)g * wstride;
    const float* bias = bbase ? (bbase + (size_t)g * bstride) : nullptr;
    float* Y = Ybase + (size_t)g * NF;
    int row0 = blockIdx.x * 64;

    __shared__ __align__(16) float Xs[64][33];
    __shared__ __align__(16) float Ws[32][128];

    int tid = threadIdx.x;
    int tx = tid & 15;   // column group: 8 cols
    int ty = tid >> 4;   // row group: 4 rows

    float acc[4][8];
#pragma unroll
    for (int m = 0; m < 4; m++)
#pragma unroll
        for (int j = 0; j < 8; j++) acc[m][j] = 0.f;

    for (int kc = 0; kc < 4; kc++) {
        int k0 = kc * 32;
        // Xs: 2048 scalars
#pragma unroll
        for (int t = 0; t < 8; t++) {
            int i = tid + t * 256;
            int r = i >> 5, k = i & 31;
            int row = row0 + r;
            Xs[r][k] = (row < N_) ? X[(size_t)row * 128 + k0 + k] : 0.f;
        }
        // Ws: 4096 scalars via float4
#pragma unroll
        for (int t = 0; t < 4; t++) {
            int i = tid + t * 256;
            int k = i >> 5, c4 = (i & 31) * 4;
            *(float4*)&Ws[k][c4] = *(const float4*)&W[(size_t)(k0 + k) * 128 + c4];
        }
        __syncthreads();
#pragma unroll
        for (int k = 0; k < 32; k++) {
            float xv[4], wv[8];
#pragma unroll
            for (int m = 0; m < 4; m++) xv[m] = Xs[ty * 4 + m][k];
#pragma unroll
            for (int j = 0; j < 8; j++) wv[j] = Ws[k][tx * 8 + j];
#pragma unroll
            for (int m = 0; m < 4; m++)
#pragma unroll
                for (int j = 0; j < 8; j++) acc[m][j] += xv[m] * wv[j];
        }
        __syncthreads();
    }

#pragma unroll
    for (int m = 0; m < 4; m++) {
        int row = row0 + ty * 4 + m;
        if (row >= N_) continue;
#pragma unroll
        for (int j = 0; j < 8; j += 4) {
            int col = tx * 8 + j;
            float* yp = &Y[(size_t)row * 128 + col];
            float4 o;
            o.x = acc[m][j]; o.y = acc[m][j + 1]; o.z = acc[m][j + 2]; o.w = acc[m][j + 3];
            if (bias) {
                o.x += bias[col]; o.y += bias[col + 1]; o.z += bias[col + 2]; o.w += bias[col + 3];
            }
            if (accumulate) {
                float4 old = *(float4*)yp;
                o.x += old.x; o.y += old.y; o.z += old.z; o.w += old.w;
            }
            *(float4*)yp = o;
        }
    }
}

// ------------------------- GCN aggregation (warp per node) ----------------
// out[d] = b + dinv[d]*(sum_{s in in(d)} dinv[s]*h[s]) + dinv[d]^2 * h[d]
__global__ void agg_k(const float* __restrict__ h, float* __restrict__ out,
                      const float* __restrict__ bias)
{
    int warp = (blockIdx.x * blockDim.x + threadIdx.x) >> 5;
    int lane = threadIdx.x & 31;
    if (warp >= N_) return;
    int g = blockIdx.y;
    int node = warp;

    const float* hg = h + (size_t)g * NF;
    const float* dv = d_dinv + g * N_;
    const int* rp = d_rowptr + g * (N_ + 1);
    const int* cg = d_col + (size_t)g * E_;

    int beg = rp[node], end = rp[node + 1];
    float4 acc = make_float4(0.f, 0.f, 0.f, 0.f);
    for (int e = beg; e < end; e++) {
        int s = cg[e];
        float w = dv[s];
        float4 v = *(const float4*)(hg + (size_t)s * F_ + lane * 4);
        acc.x += w * v.x; acc.y += w * v.y; acc.z += w * v.z; acc.w += w * v.w;
    }
    float di = dv[node];
    float di2 = di * di;
    float4 sv = *(const float4*)(hg + (size_t)node * F_ + lane * 4);
    float4 b4 = *(const float4*)(bias + lane * 4);
    float4 o;
    o.x = di * acc.x + di2 * sv.x + b4.x;
    o.y = di * acc.y + di2 * sv.y + b4.y;
    o.z = di * acc.z + di2 * sv.z + b4.z;
    o.w = di * acc.w + di2 * sv.w + b4.w;
    *(float4*)(out + (size_t)g * NF + (size_t)node * F_ + lane * 4) = o;
}

// ------------------------- dec_in ----------------------------------------
__global__ void decin_k() {
    size_t i = (size_t)blockIdx.x * blockDim.x + threadIdx.x;
    if (i >= NF) return;
    float e0 = d_enc[i], e1 = d_enc[NF + i], e2 = d_enc[2 * NF + i];
    float s = e0 + e1 + e2;
    d_decin[i]          = (s - e0) * 0.5f;
    d_decin[NF + i]     = (s - e1) * 0.5f;
    d_decin[2 * NF + i] = (s - e2) * 0.5f;
}

// ------------------------- global_vec + u ---------------------------------
__global__ void gv_reduce_k() {
    int g = blockIdx.y;
    int f = threadIdx.x;                 // 128
    int n0 = blockIdx.x * 512;
    int nend = n0 + 512; if (nend > N_) nend = N_;
    float s = 0.f;
    const float* eg = d_enc + (size_t)g * NF;
    for (int n = n0; n < nend; n++) s += eg[(size_t)n * F_ + f];
    atomicAdd(&d_gv[g * F_ + f], s);
}

__global__ void compute_u_k(const float* __restrict__ att) {
    int g = blockIdx.x;
    int dcol = threadIdx.x;              // 128
    __shared__ float sv[F_];
    float m = d_gv[g * F_ + dcol] * (1.f / (float)N_);
    sv[dcol] = 1.f / (1.f + expf(-m));
    __syncthreads();
    const float* row = att + ((size_t)g * F_ + dcol) * F_;
    float s = 0.f;
#pragma unroll 4
    for (int e = 0; e < F_; e++) s += row[e] * sv[e];
    d_u[g * F_ + dcol] = s;
}

// ------------------------- comp_re (warp per node) -------------------------
__global__ void comp_k(float* __restrict__ out) {
    __shared__ __align__(16) float su[G_ * F_];
    int tid = threadIdx.x;
    for (int i = tid; i < G_ * F_; i += blockDim.x) su[i] = d_u[i];
    __syncthreads();

    int warp = (blockIdx.x * blockDim.x + tid) >> 5;
    int lane = tid & 31;
    if (warp >= N_) return;
    int node = warp;

    float4 e[G_];
#pragma unroll
    for (int j = 0; j < G_; j++)
        e[j] = *(const float4*)(d_enc + (size_t)j * NF + (size_t)node * F_ + lane * 4);

    float dots[G_][G_];
#pragma unroll
    for (int i = 0; i < G_; i++) {
        float4 uu = *(const float4*)&su[i * F_ + lane * 4];
#pragma unroll
        for (int j = 0; j < G_; j++) {
            float p = e[j].x * uu.x + e[j].y * uu.y + e[j].z * uu.z + e[j].w * uu.w;
#pragma unroll
            for (int off = 16; off; off >>= 1) p += __shfl_xor_sync(0xFFFFFFFFu, p, off);
            dots[i][j] = p;
        }
    }
    if (lane == 0) {
#pragma unroll
        for (int i = 0; i < G_; i++) {
            float s[G_], tot = 0.f;
#pragma unroll
            for (int j = 0; j < G_; j++) { s[j] = 1.f / (1.f + expf(-dots[i][j])); tot += s[j]; }
            float inv = 1.f / tot;
#pragma unroll
            for (int j = 0; j < G_; j++) out[(size_t)node * 9 + i * 3 + j] = s[j] * inv;
        }
    }
}

// ------------------------- fuse_feat / used_feat ---------------------------
__global__ void fuse_used_k(float* __restrict__ out) {
    size_t i = (size_t)blockIdx.x * blockDim.x + threadIdx.x;
    if (i >= NF) return;
    float a = (d_efin[i] + d_efin[NF + i] + d_efin[2 * NF + i]) * (1.f / 3.f);
    float b = (d_enc[i]  + d_enc[NF + i]  + d_enc[2 * NF + i])  * (1.f / 3.f);
    out[i] = 1.f / (1.f + expf(-a));
    out[NF + i] = (b > 0.f) ? b : expm1f(b);
}

// ------------------------- obf partial reduction ----------------------------
__global__ void obf_reduce_k() {
    float loc[9];
#pragma unroll
    for (int q = 0; q < 9; q++) loc[q] = 0.f;
    size_t stride = (size_t)gridDim.x * blockDim.x;
    for (size_t i = (size_t)blockIdx.x * blockDim.x + threadIdx.x; i < NF; i += stride) {
#pragma unroll
        for (int g = 0; g < G_; g++) {
            size_t gi = (size_t)g * NF + i;
            float dp = d_pre[gi] - d_own2[gi];   loc[g]     += dp * dp;
            float dc = d_conv1[gi] - d_own1[gi]; loc[3 + g] += dc * dc;
        }
        float e0 = d_efin[i], e1 = d_efin[NF + i], e2 = d_efin[2 * NF + i];
        float d01 = e0 - e1, d02 = e0 - e2, d12 = e1 - e2;
        loc[6] += d01 * d01; loc[7] += d02 * d02; loc[8] += d12 * d12;
    }
    __shared__ float red[256];
    for (int q = 0; q < 9; q++) {
        red[threadIdx.x] = loc[q];
        __syncthreads();
        for (int s = 128; s > 0; s >>= 1) {
            if (threadIdx.x < s) red[threadIdx.x] += red[threadIdx.x + s];
            __syncthreads();
        }
        if (threadIdx.x == 0) atomicAdd(&d_parts[q], red[0]);
        __syncthreads();
    }
}

__global__ void finalize_k(float* __restrict__ out) {
    float obf1 = 0.f;
#pragma unroll
    for (int g = 0; g < G_; g++)
        obf1 += 0.5f * (sqrtf(d_parts[g]) + sqrtf(d_parts[3 + g]));
    float obf0 = 2.f * (sqrtf(d_parts[6]) + sqrtf(d_parts[7]) + sqrtf(d_parts[8]));
    out[2 * NF + 9 * (size_t)N_]     = obf1;
    out[2 * NF + 9 * (size_t)N_ + 1] = obf0;
}

// ------------------------- host launcher -----------------------------------
extern "C" void kernel_launch(void* const* d_in, const int* in_sizes, int n_in,
                              void* d_out, int out_size)
{
    const float* x       = (const float*)d_in[0];
    const float* fc1_w   = (const float*)d_in[1];
    const float* fc1_b   = (const float*)d_in[2];
    const float* w_conv1 = (const float*)d_in[3];
    const float* b_conv1 = (const float*)d_in[4];
    const float* w_conv2 = (const float*)d_in[5];
    const float* b_conv2 = (const float*)d_in[6];
    const float* w_dconv1 = (const float*)d_in[7];
    const float* b_dconv1 = (const float*)d_in[8];
    const float* w_dconv2 = (const float*)d_in[9];
    const float* b_dconv2 = (const float*)d_in[10];
    const float* fc2_w   = (const float*)d_in[11];
    const float* fc2_b   = (const float*)d_in[12];
    const float* att_w   = (const float*)d_in[13];
    const void*  edges   = (const void*)d_in[14];
    float* out = (float*)d_out;

    float *pre, *conv1, *enc, *own1, *own2, *oth2, *tmp, *decin, *efin;
    cudaGetSymbolAddress((void**)&pre,   d_pre);
    cudaGetSymbolAddress((void**)&conv1, d_conv1);
    cudaGetSymbolAddress((void**)&enc,   d_enc);
    cudaGetSymbolAddress((void**)&own1,  d_own1);
    cudaGetSymbolAddress((void**)&own2,  d_own2);
    cudaGetSymbolAddress((void**)&oth2,  d_oth2);
    cudaGetSymbolAddress((void**)&tmp,   d_tmp);
    cudaGetSymbolAddress((void**)&decin, d_decin);
    cudaGetSymbolAddress((void**)&efin,  d_efin);

    const int TB = 256;
    dim3 gemm_grid((N_ + 63) / 64, G_);
    dim3 agg_grid((N_ + 7) / 8, G_);
    int nf_blocks = (int)((NF + TB - 1) / TB);

    // --- edge dtype detection + CSR build ---
    detect_dtype_k<<<1, 256>>>(edges);
    zero_deg_k<<<(G_ * N_ + TB - 1) / TB, TB>>>();
    zero_small_k<<<1, 512>>>();
    count_deg_k<<<(G_ * E_ + TB - 1) / TB, TB>>>(edges);
    dinv_k<<<(G_ * N_ + TB - 1) / TB, TB>>>();
    scan_rowptr_k<<<G_, 1024>>>();
    init_cur_k<<<(G_ * N_ + TB - 1) / TB, TB>>>();
    fill_csr_k<<<(G_ * E_ + TB - 1) / TB, TB>>>(edges);

    // --- encoder ---
    gemm_n128_k<<<gemm_grid, TB>>>(x, fc1_w, fc1_b, pre, F_ * F_, F_, 0);
    gemm_n128_k<<<gemm_grid, TB>>>(pre, w_conv1, nullptr, tmp, 0, 0, 0);
    agg_k<<<agg_grid, TB>>>(tmp, conv1, b_conv1);
    gemm_n128_k<<<gemm_grid, TB>>>(conv1, w_conv2, nullptr, tmp, 0, 0, 0);
    agg_k<<<agg_grid, TB>>>(tmp, enc, b_conv2);

    // --- global vec + attention u ---
    gv_reduce_k<<<dim3((N_ + 511) / 512, G_), F_>>>();
    compute_u_k<<<G_, F_>>>(att_w);

    // --- decoder ---
    decin_k<<<nf_blocks, TB>>>();
    gemm_n128_k<<<gemm_grid, TB>>>(enc, w_dconv1, nullptr, tmp, 0, 0, 0);
    agg_k<<<agg_grid, TB>>>(tmp, own1, b_dconv1);
    gemm_n128_k<<<gemm_grid, TB>>>(own1, w_dconv2, nullptr, tmp, 0, 0, 0);
    agg_k<<<agg_grid, TB>>>(tmp, own2, b_dconv2);
    gemm_n128_k<<<gemm_grid, TB>>>(decin, w_dconv1, nullptr, tmp, 0, 0, 0);
    agg_k<<<agg_grid, TB>>>(tmp, decin, b_dconv1);
    gemm_n128_k<<<gemm_grid, TB>>>(decin, w_dconv2, nullptr, tmp, 0, 0, 0);
    agg_k<<<agg_grid, TB>>>(tmp, oth2, b_dconv2);

    // --- each_fin = [own2, oth2] @ fc2_w + fc2_b (split-K accumulate) ---
    gemm_n128_k<<<gemm_grid, TB>>>(own2, fc2_w, fc2_b, efin, 0, 0, 0);
    gemm_n128_k<<<gemm_grid, TB>>>(oth2, fc2_w + F_ * F_, nullptr, efin, 0, 0, 1);

    // --- outputs ---
    fuse_used_k<<<nf_blocks, TB>>>(out);
    comp_k<<<(N_ + 7) / 8, TB>>>(out + 2 * NF);
    obf_reduce_k<<<512, TB>>>();
    finalize_k<<<1, 1>>>(out);
}

// round 4
// speedup vs baseline: 2.1375x; 2.1375x over previous
#include <cuda_runtime.h>
#include <cuda_bf16.h>
#include <math.h>
#include <stdint.h>

#define N_ 50000
#define F_ 128
#define G_ 3
#define E_ 600000
#define NF ((size_t)N_ * F_)

// ------------------------- static device scratch -------------------------
__device__ __align__(16) float d_pre  [G_ * N_ * F_];
__device__ __align__(16) float d_conv1[G_ * N_ * F_];
__device__ __align__(16) float d_enc  [G_ * N_ * F_];
__device__ __align__(16) float d_own1 [G_ * N_ * F_];
__device__ __align__(16) float d_own2 [G_ * N_ * F_];
__device__ __align__(16) float d_oth2 [G_ * N_ * F_];
__device__ __align__(16) float d_tmp  [G_ * N_ * F_];
__device__ __align__(16) float d_decin[G_ * N_ * F_];
__device__ __align__(16) float d_efin [G_ * N_ * F_];

__device__ int   d_deg   [G_ * N_];
__device__ int   d_rowptr[G_ * (N_ + 1)];
__device__ int   d_cur   [G_ * N_];
__device__ int   d_col   [G_ * E_];
__device__ __align__(16) float d_dinv  [G_ * N_];
__device__ float d_gv    [G_ * F_];
__device__ __align__(16) float d_u     [G_ * F_];
__device__ float d_parts [16];
__device__ int   d_e64;      // 1 if edge buffer is int64, 0 if int32

// ------------------------- edge dtype detection ---------------------------
__global__ void detect_dtype_k(const void* __restrict__ edges) {
    const unsigned int* w = (const unsigned int*)edges;
    __shared__ int any;
    if (threadIdx.x == 0) any = 0;
    __syncthreads();
    for (int i = threadIdx.x; i < 2048; i += blockDim.x)
        if (w[2 * i + 1] != 0u) any = 1;
    __syncthreads();
    if (threadIdx.x == 0) d_e64 = any ? 0 : 1;
}

__device__ __forceinline__ int load_edge(const void* edges, size_t idx, int e64) {
    if (e64) return (int)((const long long*)edges)[idx];
    return ((const int*)edges)[idx];
}

// ------------------------- small utility kernels -------------------------
__global__ void zero_deg_k() {
    int i = blockIdx.x * blockDim.x + threadIdx.x;
    if (i < G_ * N_) d_deg[i] = 0;
}

__global__ void zero_small_k() {
    int i = threadIdx.x;
    if (i < G_ * F_) d_gv[i] = 0.f;
    if (i < 16) d_parts[i] = 0.f;
}

__global__ void count_deg_k(const void* __restrict__ edges) {
    int i = blockIdx.x * blockDim.x + threadIdx.x;
    if (i >= G_ * E_) return;
    int e64 = d_e64;
    int g = i / E_, e = i - g * E_;
    int dst = load_edge(edges, (size_t)g * 2 * E_ + E_ + e, e64);
    atomicAdd(&d_deg[g * N_ + dst], 1);
}

__global__ void dinv_k() {
    int i = blockIdx.x * blockDim.x + threadIdx.x;
    if (i < G_ * N_) d_dinv[i] = rsqrtf((float)(d_deg[i] + 1));
}

__global__ void scan_rowptr_k() {
    int g = blockIdx.x;
    __shared__ int sbuf[1024];
    __shared__ int soff;
    int tid = threadIdx.x;
    if (tid == 0) { soff = 0; d_rowptr[g * (N_ + 1)] = 0; }
    __syncthreads();
    for (int base = 0; base < N_; base += 1024) {
        int idx = base + tid;
        int v = (idx < N_) ? d_deg[g * N_ + idx] : 0;
        sbuf[tid] = v;
        __syncthreads();
        for (int s = 1; s < 1024; s <<= 1) {
            int t = (tid >= s) ? sbuf[tid - s] : 0;
            __syncthreads();
            sbuf[tid] += t;
            __syncthreads();
        }
        if (idx < N_) d_rowptr[g * (N_ + 1) + idx + 1] = soff + sbuf[tid];
        __syncthreads();
        if (tid == 0) soff += sbuf[1023];
        __syncthreads();
    }
}

__global__ void init_cur_k() {
    int i = blockIdx.x * blockDim.x + threadIdx.x;
    if (i >= G_ * N_) return;
    int g = i / N_, n = i - g * N_;
    d_cur[i] = d_rowptr[g * (N_ + 1) + n];
}

__global__ void fill_csr_k(const void* __restrict__ edges) {
    int i = blockIdx.x * blockDim.x + threadIdx.x;
    if (i >= G_ * E_) return;
    int e64 = d_e64;
    int g = i / E_, e = i - g * E_;
    int src = load_edge(edges, (size_t)g * 2 * E_ + e, e64);
    int dst = load_edge(edges, (size_t)g * 2 * E_ + E_ + e, e64);
    int pos = atomicAdd(&d_cur[g * N_ + dst], 1);
    d_col[(size_t)g * E_ + pos] = src;
}

// ------------------------- tf32 tensor-core GEMM --------------------------
// Y[N,128] = X[N,128] @ W[128,128] (+ X2 @ W2) (+ bias)
// block tile 128x128, 256 threads = 8 warps (4m x 2n), warp tile 32x64.
__device__ __forceinline__ uint32_t f2tf32(float x) {
    uint32_t r; asm("cvt.rna.tf32.f32 %0, %1;" : "=r"(r) : "f"(x)); return r;
}

__device__ __forceinline__ void mma_tf32(float* c, const uint32_t* a,
                                         uint32_t b0, uint32_t b1) {
    asm volatile(
        "mma.sync.aligned.m16n8k8.row.col.f32.tf32.tf32.f32 "
        "{%0,%1,%2,%3}, {%4,%5,%6,%7}, {%8,%9}, {%0,%1,%2,%3};"
        : "+f"(c[0]), "+f"(c[1]), "+f"(c[2]), "+f"(c[3])
        : "r"(a[0]), "r"(a[1]), "r"(a[2]), "r"(a[3]), "r"(b0), "r"(b1));
}

#define XS_STRIDE 36   // bank = 4*(lane>>2) + (lane&3): conflict-free A reads
#define WS_STRIDE 136  // bank = 8*(lane&3) + (lane>>2): conflict-free B reads

__global__ void __launch_bounds__(256) gemm_tf32_k(
    const float* __restrict__ Xbase, const float* __restrict__ Wbase,
    const float* __restrict__ bbase, float* __restrict__ Ybase,
    const float* __restrict__ X2base, const float* __restrict__ W2base,
    int wstride, int bstride)
{
    int g = blockIdx.y;
    const float* X  = Xbase + (size_t)g * NF;
    const float* W  = Wbase + (size_t)g * wstride;
    const float* X2 = X2base ? (X2base + (size_t)g * NF) : nullptr;
    const float* bias = bbase ? (bbase + (size_t)g * bstride) : nullptr;
    float* Y = Ybase + (size_t)g * NF;
    int row0 = blockIdx.x * 128;

    __shared__ __align__(16) uint32_t Xs[128][XS_STRIDE];  // [row][k]
    __shared__ __align__(16) uint32_t Ws[32][WS_STRIDE];   // [k][col]

    int tid = threadIdx.x;
    int lane = tid & 31;
    int wid = tid >> 5;
    int wm = (wid >> 1) * 32;     // warp row offset in block tile
    int wn = (wid & 1) * 64;      // warp col offset

    float acc[2][8][4];
#pragma unroll
    for (int mt = 0; mt < 2; mt++)
#pragma unroll
        for (int nt = 0; nt < 8; nt++)
#pragma unroll
            for (int q = 0; q < 4; q++) acc[mt][nt][q] = 0.f;

    int nchunks = X2 ? 8 : 4;
    for (int chunk = 0; chunk < nchunks; chunk++) {
        const float* Xc; const float* Wc; int k0;
        if (chunk < 4) { Xc = X;  Wc = W;      k0 = chunk * 32; }
        else           { Xc = X2; Wc = W2base; k0 = (chunk - 4) * 32; }

        // load X tile 128x32 (convert to tf32)
#pragma unroll
        for (int t = 0; t < 4; t++) {
            int idx = tid + t * 256;              // 0..1023 float4 slots
            int r = idx >> 3, c = (idx & 7) * 4;
            int row = row0 + r;
            float4 v = make_float4(0.f, 0.f, 0.f, 0.f);
            if (row < N_) v = *(const float4*)(Xc + (size_t)row * 128 + k0 + c);
            uint4 u;
            u.x = f2tf32(v.x); u.y = f2tf32(v.y); u.z = f2tf32(v.z); u.w = f2tf32(v.w);
            *(uint4*)&Xs[r][c] = u;
        }
        // load W tile 32x128
#pragma unroll
        for (int t = 0; t < 4; t++) {
            int idx = tid + t * 256;
            int k = idx >> 5, c = (idx & 31) * 4;
            float4 v = *(const float4*)(Wc + (size_t)(k0 + k) * 128 + c);
            uint4 u;
            u.x = f2tf32(v.x); u.y = f2tf32(v.y); u.z = f2tf32(v.z); u.w = f2tf32(v.w);
            *(uint4*)&Ws[k][c] = u;
        }
        __syncthreads();

#pragma unroll
        for (int kk = 0; kk < 4; kk++) {
            int kb = kk * 8;
            uint32_t a[2][4];
#pragma unroll
            for (int mt = 0; mt < 2; mt++) {
                int r = wm + mt * 16 + (lane >> 2);
                int c = kb + (lane & 3);
                a[mt][0] = Xs[r][c];
                a[mt][1] = Xs[r + 8][c];
                a[mt][2] = Xs[r][c + 4];
                a[mt][3] = Xs[r + 8][c + 4];
            }
#pragma unroll
            for (int nt = 0; nt < 8; nt++) {
                int col = wn + nt * 8 + (lane >> 2);
                uint32_t b0 = Ws[kb + (lane & 3)][col];
                uint32_t b1 = Ws[kb + (lane & 3) + 4][col];
                mma_tf32(acc[0][nt], a[0], b0, b1);
                mma_tf32(acc[1][nt], a[1], b0, b1);
            }
        }
        __syncthreads();
    }

    // epilogue
#pragma unroll
    for (int mt = 0; mt < 2; mt++) {
        int r0 = row0 + wm + mt * 16 + (lane >> 2);
        int r1 = r0 + 8;
#pragma unroll
        for (int nt = 0; nt < 8; nt++) {
            int cb = wn + nt * 8 + 2 * (lane & 3);
            float bx = 0.f, by = 0.f;
            if (bias) { bx = bias[cb]; by = bias[cb + 1]; }
            if (r0 < N_) {
                float2 o = make_float2(acc[mt][nt][0] + bx, acc[mt][nt][1] + by);
                *(float2*)(Y + (size_t)r0 * 128 + cb) = o;
            }
            if (r1 < N_) {
                float2 o = make_float2(acc[mt][nt][2] + bx, acc[mt][nt][3] + by);
                *(float2*)(Y + (size_t)r1 * 128 + cb) = o;
            }
        }
    }
}

// ------------------------- GCN aggregation (warp per node) ----------------
__global__ void agg_k(const float* __restrict__ h, float* __restrict__ out,
                      const float* __restrict__ bias)
{
    int warp = (blockIdx.x * blockDim.x + threadIdx.x) >> 5;
    int lane = threadIdx.x & 31;
    if (warp >= N_) return;
    int g = blockIdx.y;
    int node = warp;

    const float* hg = h + (size_t)g * NF;
    const float* dv = d_dinv + g * N_;
    const int* rp = d_rowptr + g * (N_ + 1);
    const int* cg = d_col + (size_t)g * E_;

    int beg = rp[node], end = rp[node + 1];
    float4 acc = make_float4(0.f, 0.f, 0.f, 0.f);
    for (int e = beg; e < end; e++) {
        int s = cg[e];
        float w = dv[s];
        float4 v = *(const float4*)(hg + (size_t)s * F_ + lane * 4);
        acc.x += w * v.x; acc.y += w * v.y; acc.z += w * v.z; acc.w += w * v.w;
    }
    float di = dv[node];
    float di2 = di * di;
    float4 sv = *(const float4*)(hg + (size_t)node * F_ + lane * 4);
    float4 b4 = *(const float4*)(bias + lane * 4);
    float4 o;
    o.x = di * acc.x + di2 * sv.x + b4.x;
    o.y = di * acc.y + di2 * sv.y + b4.y;
    o.z = di * acc.z + di2 * sv.z + b4.z;
    o.w = di * acc.w + di2 * sv.w + b4.w;
    *(float4*)(out + (size_t)g * NF + (size_t)node * F_ + lane * 4) = o;
}

// ------------------------- oth-path input from t1 = enc@W1 -----------------
__global__ void oth_in_k() {
    size_t i = (size_t)blockIdx.x * blockDim.x + threadIdx.x;
    if (i >= NF) return;
    float t0 = d_tmp[i], t1 = d_tmp[NF + i], t2 = d_tmp[2 * NF + i];
    float s = t0 + t1 + t2;
    d_decin[i]          = (s - t0) * 0.5f;
    d_decin[NF + i]     = (s - t1) * 0.5f;
    d_decin[2 * NF + i] = (s - t2) * 0.5f;
}

// ------------------------- global_vec + u ---------------------------------
__global__ void gv_reduce_k() {
    int g = blockIdx.y;
    int f = threadIdx.x;                 // 128
    int n0 = blockIdx.x * 512;
    int nend = n0 + 512; if (nend > N_) nend = N_;
    float s = 0.f;
    const float* eg = d_enc + (size_t)g * NF;
    for (int n = n0; n < nend; n++) s += eg[(size_t)n * F_ + f];
    atomicAdd(&d_gv[g * F_ + f], s);
}

__global__ void compute_u_k(const float* __restrict__ att) {
    int g = blockIdx.x;
    int dcol = threadIdx.x;              // 128
    __shared__ float sv[F_];
    float m = d_gv[g * F_ + dcol] * (1.f / (float)N_);
    sv[dcol] = 1.f / (1.f + expf(-m));
    __syncthreads();
    const float* row = att + ((size_t)g * F_ + dcol) * F_;
    float s = 0.f;
#pragma unroll 4
    for (int e = 0; e < F_; e++) s += row[e] * sv[e];
    d_u[g * F_ + dcol] = s;
}

// ------------------------- comp_re (warp per node) -------------------------
__global__ void comp_k(float* __restrict__ out) {
    __shared__ __align__(16) float su[G_ * F_];
    int tid = threadIdx.x;
    for (int i = tid; i < G_ * F_; i += blockDim.x) su[i] = d_u[i];
    __syncthreads();

    int warp = (blockIdx.x * blockDim.x + tid) >> 5;
    int lane = tid & 31;
    if (warp >= N_) return;
    int node = warp;

    float4 e[G_];
#pragma unroll
    for (int j = 0; j < G_; j++)
        e[j] = *(const float4*)(d_enc + (size_t)j * NF + (size_t)node * F_ + lane * 4);

    float dots[G_][G_];
#pragma unroll
    for (int i = 0; i < G_; i++) {
        float4 uu = *(const float4*)&su[i * F_ + lane * 4];
#pragma unroll
        for (int j = 0; j < G_; j++) {
            float p = e[j].x * uu.x + e[j].y * uu.y + e[j].z * uu.z + e[j].w * uu.w;
#pragma unroll
            for (int off = 16; off; off >>= 1) p += __shfl_xor_sync(0xFFFFFFFFu, p, off);
            dots[i][j] = p;
        }
    }
    if (lane == 0) {
#pragma unroll
        for (int i = 0; i < G_; i++) {
            float s[G_], tot = 0.f;
#pragma unroll
            for (int j = 0; j < G_; j++) { s[j] = 1.f / (1.f + expf(-dots[i][j])); tot += s[j]; }
            float inv = 1.f / tot;
#pragma unroll
            for (int j = 0; j < G_; j++) out[(size_t)node * 9 + i * 3 + j] = s[j] * inv;
        }
    }
}

// ------------------------- fuse_feat / used_feat ---------------------------
__global__ void fuse_used_k(float* __restrict__ out) {
    size_t i = (size_t)blockIdx.x * blockDim.x + threadIdx.x;
    if (i >= NF) return;
    float a = (d_efin[i] + d_efin[NF + i] + d_efin[2 * NF + i]) * (1.f / 3.f);
    float b = (d_enc[i]  + d_enc[NF + i]  + d_enc[2 * NF + i])  * (1.f / 3.f);
    out[i] = 1.f / (1.f + expf(-a));
    out[NF + i] = (b > 0.f) ? b : expm1f(b);
}

// ------------------------- obf partial reduction ----------------------------
__global__ void obf_reduce_k() {
    float loc[9];
#pragma unroll
    for (int q = 0; q < 9; q++) loc[q] = 0.f;
    size_t stride = (size_t)gridDim.x * blockDim.x;
    for (size_t i = (size_t)blockIdx.x * blockDim.x + threadIdx.x; i < NF; i += stride) {
#pragma unroll
        for (int g = 0; g < G_; g++) {
            size_t gi = (size_t)g * NF + i;
            float dp = d_pre[gi] - d_own2[gi];   loc[g]     += dp * dp;
            float dc = d_conv1[gi] - d_own1[gi]; loc[3 + g] += dc * dc;
        }
        float e0 = d_efin[i], e1 = d_efin[NF + i], e2 = d_efin[2 * NF + i];
        float d01 = e0 - e1, d02 = e0 - e2, d12 = e1 - e2;
        loc[6] += d01 * d01; loc[7] += d02 * d02; loc[8] += d12 * d12;
    }
    __shared__ float red[256];
    for (int q = 0; q < 9; q++) {
        red[threadIdx.x] = loc[q];
        __syncthreads();
        for (int s = 128; s > 0; s >>= 1) {
            if (threadIdx.x < s) red[threadIdx.x] += red[threadIdx.x + s];
            __syncthreads();
        }
        if (threadIdx.x == 0) atomicAdd(&d_parts[q], red[0]);
        __syncthreads();
    }
}

__global__ void finalize_k(float* __restrict__ out) {
    float obf1 = 0.f;
#pragma unroll
    for (int g = 0; g < G_; g++)
        obf1 += 0.5f * (sqrtf(d_parts[g]) + sqrtf(d_parts[3 + g]));
    float obf0 = 2.f * (sqrtf(d_parts[6]) + sqrtf(d_parts[7]) + sqrtf(d_parts[8]));
    out[2 * NF + 9 * (size_t)N_]     = obf1;
    out[2 * NF + 9 * (size_t)N_ + 1] = obf0;
}

// ------------------------- host launcher -----------------------------------
extern "C" void kernel_launch(void* const* d_in, const int* in_sizes, int n_in,
                              void* d_out, int out_size)
{
    const float* x       = (const float*)d_in[0];
    const float* fc1_w   = (const float*)d_in[1];
    const float* fc1_b   = (const float*)d_in[2];
    const float* w_conv1 = (const float*)d_in[3];
    const float* b_conv1 = (const float*)d_in[4];
    const float* w_conv2 = (const float*)d_in[5];
    const float* b_conv2 = (const float*)d_in[6];
    const float* w_dconv1 = (const float*)d_in[7];
    const float* b_dconv1 = (const float*)d_in[8];
    const float* w_dconv2 = (const float*)d_in[9];
    const float* b_dconv2 = (const float*)d_in[10];
    const float* fc2_w   = (const float*)d_in[11];
    const float* fc2_b   = (const float*)d_in[12];
    const float* att_w   = (const float*)d_in[13];
    const void*  edges   = (const void*)d_in[14];
    float* out = (float*)d_out;

    float *pre, *conv1, *enc, *own1, *own2, *oth2, *tmp, *decin, *efin;
    cudaGetSymbolAddress((void**)&pre,   d_pre);
    cudaGetSymbolAddress((void**)&conv1, d_conv1);
    cudaGetSymbolAddress((void**)&enc,   d_enc);
    cudaGetSymbolAddress((void**)&own1,  d_own1);
    cudaGetSymbolAddress((void**)&own2,  d_own2);
    cudaGetSymbolAddress((void**)&oth2,  d_oth2);
    cudaGetSymbolAddress((void**)&tmp,   d_tmp);
    cudaGetSymbolAddress((void**)&decin, d_decin);
    cudaGetSymbolAddress((void**)&efin,  d_efin);

    const int TB = 256;
    dim3 gemm_grid((N_ + 127) / 128, G_);
    dim3 agg_grid((N_ + 7) / 8, G_);
    int nf_blocks = (int)((NF + TB - 1) / TB);

    // --- edge dtype detection + CSR build ---
    detect_dtype_k<<<1, 256>>>(edges);
    zero_deg_k<<<(G_ * N_ + TB - 1) / TB, TB>>>();
    zero_small_k<<<1, 512>>>();
    count_deg_k<<<(G_ * E_ + TB - 1) / TB, TB>>>(edges);
    dinv_k<<<(G_ * N_ + TB - 1) / TB, TB>>>();
    scan_rowptr_k<<<G_, 1024>>>();
    init_cur_k<<<(G_ * N_ + TB - 1) / TB, TB>>>();
    fill_csr_k<<<(G_ * E_ + TB - 1) / TB, TB>>>(edges);

    // --- encoder ---
    gemm_tf32_k<<<gemm_grid, TB>>>(x, fc1_w, fc1_b, pre, nullptr, nullptr, F_ * F_, F_);
    gemm_tf32_k<<<gemm_grid, TB>>>(pre, w_conv1, nullptr, tmp, nullptr, nullptr, 0, 0);
    agg_k<<<agg_grid, TB>>>(tmp, conv1, b_conv1);
    gemm_tf32_k<<<gemm_grid, TB>>>(conv1, w_conv2, nullptr, tmp, nullptr, nullptr, 0, 0);
    agg_k<<<agg_grid, TB>>>(tmp, enc, b_conv2);

    // --- global vec + attention u ---
    gv_reduce_k<<<dim3((N_ + 511) / 512, G_), F_>>>();
    compute_u_k<<<G_, F_>>>(att_w);

    // --- decoder: t1 = enc@W1 shared between own and oth paths ---
    gemm_tf32_k<<<gemm_grid, TB>>>(enc, w_dconv1, nullptr, tmp, nullptr, nullptr, 0, 0);
    oth_in_k<<<nf_blocks, TB>>>();                 // decin = (sum(t1) - t1)/2
    agg_k<<<agg_grid, TB>>>(tmp, own1, b_dconv1);  // own1
    agg_k<<<agg_grid, TB>>>(decin, tmp, b_dconv1); // tmp := oth1
    gemm_tf32_k<<<gemm_grid, TB>>>(own1, w_dconv2, nullptr, decin, nullptr, nullptr, 0, 0);
    agg_k<<<agg_grid, TB>>>(decin, own2, b_dconv2);
    gemm_tf32_k<<<gemm_grid, TB>>>(tmp, w_dconv2, nullptr, decin, nullptr, nullptr, 0, 0);
    agg_k<<<agg_grid, TB>>>(decin, oth2, b_dconv2);

    // --- each_fin = [own2, oth2] @ fc2_w + fc2_b (single fused K=256 GEMM) ---
    gemm_tf32_k<<<gemm_grid, TB>>>(own2, fc2_w, fc2_b, efin, oth2, fc2_w + F_ * F_, 0, 0);

    // --- outputs ---
    fuse_used_k<<<nf_blocks, TB>>>(out);
    comp_k<<<(N_ + 7) / 8, TB>>>(out + 2 * NF);
    obf_reduce_k<<<512, TB>>>();
    finalize_k<<<1, 1>>>(out);
}